// round 15
// baseline (speedup 1.0000x reference)
#include <cuda_runtime.h>
#include <cuda_fp16.h>
#include <cstdint>

#define HDIM 64
#define DDIM 32

__device__ __forceinline__ float sigmoid_fast(float z) {
    float e, r;
    asm("ex2.approx.f32 %0, %1;" : "=f"(e) : "f"(z * -1.44269504088896340736f));
    asm("rcp.approx.f32 %0, %1;" : "=f"(r) : "f"(1.0f + e));
    return r;
}

// pack two fp32 into half2 {lo, hi}
__device__ __forceinline__ uint32_t pack_h2(float lo, float hi) {
    uint32_t d;
    asm("cvt.rn.f16x2.f32 %0, %1, %2;" : "=r"(d) : "f"(hi), "f"(lo));
    return d;
}

__device__ __forceinline__ void prefetch_l2(const void* p) {
    asm volatile("prefetch.global.L2 [%0];" :: "l"(p));
}

__device__ __forceinline__ void mma_f16(float* c, uint32_t a0, uint32_t a1,
                                        uint32_t a2, uint32_t a3,
                                        uint32_t b0, uint32_t b1) {
    asm volatile(
        "mma.sync.aligned.m16n8k16.row.col.f32.f16.f16.f32 "
        "{%0,%1,%2,%3}, {%4,%5,%6,%7}, {%8,%9}, {%0,%1,%2,%3};"
        : "+f"(c[0]), "+f"(c[1]), "+f"(c[2]), "+f"(c[3])
        : "r"(a0), "r"(a1), "r"(a2), "r"(a3), "r"(b0), "r"(b1));
}

// ---------------------------------------------------------------------------
// Single fused kernel, fp16 MMA (m16n8k16), FULL B resident in registers
// (8 n-tiles x 4 S x uint2 = 64 regs) -- each warp owns 16 rows x all 64 cols.
// 2 CTAs/SM, 8 warps, chunk = 128 rows per CTA iteration.
// R13: zero-register L2 prefetch of next chunk (WIN 66->61us).
// R14: __ldcs/__stcs streaming policy + hoisted idx fixup (WIN 61->60us).
// R15: balanced chunk partition (old ceil-div gave CTAs 0..278 14 chunks,
// CTA 279 one, 280..295 zero -> makespan 14 vs 13.2) + prefetch distance 2.
//
// out[r] = sigmoid(W2 @ h[r] + d2[r]*u2 + c),  d2[r] = ||goal[r]-position[r]||,
// row idx passed through (post-loop fixup); goal_out written by CTA 0.
//
// K-permutation (same perm on A cols and B k-rows; exact):
//   frag k16-slice S <-> phys cols {16S+4tau .. 16S+4tau+3} per lane
// N-permutation: phys J = sgg*16 + 4*tau + e <-> (nt = 2*sgg + (e>>1), 2tau+(e&1))
//   => every load LDG.128, every store STG.128, constants via float4.
// ---------------------------------------------------------------------------

__global__ __launch_bounds__(256, 2)
void gate_kernel(const float* __restrict__ h,
                 const float* __restrict__ ghs,
                 const float* __restrict__ goal,
                 const float* __restrict__ position,
                 const float* __restrict__ W_emb,
                 const float* __restrict__ b_emb,
                 const float* __restrict__ W_fc,
                 const float* __restrict__ b_fc,
                 const int* __restrict__ idx_ptr,
                 float* __restrict__ out, int n)
{
    __shared__ __align__(16) float sC[HDIM];
    __shared__ __align__(16) float sU[HDIM];

    const int t = threadIdx.x;
    const int idx = idx_ptr[0];
    const int w    = t >> 5;         // 0..7 : 16-row group within 128-row chunk
    const int lane = t & 31;
    const int g    = lane >> 2;      // 0..7
    const int tau  = lane & 3;       // 0..3

    // ---- per-CTA precompute of c[j], u2[j] (threads 0..63) ----
    if (t < HDIM) {
        const int j = t;
        const float* Wj = W_fc + j * 192;
        const float* hi = h + (size_t)idx * HDIM;
        float c0 = 0.f;
        #pragma unroll 8
        for (int k = 0; k < HDIM; k++) c0 += Wj[k] * hi[k];
        float u1 = 0.f, u2 = 0.f, cb = 0.f;
        #pragma unroll 8
        for (int d = 0; d < DDIM; d++) {
            float ws = W_emb[2 * d] + W_emb[2 * d + 1];
            u1 += Wj[128 + d] * ws;
            u2 += Wj[160 + d] * ws;
            cb += (Wj[128 + d] + Wj[160 + d]) * b_emb[d];
        }
        float c = c0 + b_fc[j] + cb;
        sC[j] = c;
        sU[j] = u2;

        if (blockIdx.x == 0) {
            float wg = 0.f;
            #pragma unroll 8
            for (int k = 0; k < HDIM; k++) wg += Wj[64 + k] * ghs[k];
            float px = position[2 * idx], py = position[2 * idx + 1];
            float gx = goal[2 * idx],     gy = goal[2 * idx + 1];
            float ddx = px - gx, ddy = py - gy;
            float dgn = sqrtf(ddx * ddx + ddy * ddy);
            float zg = c + wg + dgn * (u1 + u2);
            out[(size_t)n * HDIM + j] = 1.0f / (1.0f + expf(-zg));
        }
    }

    // ---- FULL B -> registers (per warp, once), fp16: 64 regs ----
    uint2 bf[8][4];
    #pragma unroll
    for (int nt = 0; nt < 8; nt++) {
        int j = (nt >> 1) * 16 + 4 * (g >> 1) + 2 * (nt & 1) + (g & 1);
        const float* Wrow = W_fc + (size_t)j * 192 + 64 + 4 * tau;
        #pragma unroll
        for (int S = 0; S < 4; S++) {
            float4 bv = *(const float4*)(Wrow + 16 * S);
            bf[nt][S].x = pack_h2(bv.x, bv.y);
            bf[nt][S].y = pack_h2(bv.z, bv.w);
        }
    }
    __syncthreads();

    const float2* goal2 = (const float2*)goal;
    const float2* pos2  = (const float2*)position;
    const float4* h4    = (const float4*)h;
    float4* out4        = (float4*)out;
    const float4* sC4   = (const float4*)sC;
    const float4* sU4   = (const float4*)sU;

    // ---- balanced chunk partition: first r CTAs get q+1 chunks ----
    const int nfull = n >> 7;
    const int nch = nfull + ((n & 127) ? 1 : 0);
    const int q = nch / gridDim.x;
    const int r = nch - q * gridDim.x;
    const int bid = blockIdx.x;
    const int cA = bid * q + (bid < r ? bid : r);
    const int cB = cA + q + (bid < r ? 1 : 0);
    if (cA >= cB) return;

    int rg = cA * 128 + w * 16 + g;
    const float4* hgp = h4 + (size_t)rg * 16 + tau;   // row rg, float4 col tau
    const float2* gp  = goal2 + rg;
    const float2* pp  = pos2 + rg;
    float4* op        = out4 + (size_t)rg * 16;

    // prefetch base: warp's 16-row block start. Lane l covers line
    // (row = l>>1, half = l&1): 16 rows x 2 x 128B = this warp's entire A slice.
    const char* pfb = (const char*)(hgp - tau - (size_t)g * 16) + (size_t)(lane >> 1) * 256
                      + (size_t)(lane & 1) * 128;

    // pre-warm chunk cA+1 (distance-2 steady state covers cA+2 onward)
    if (cA + 1 < nfull) {
        prefetch_l2(pfb + 32768);
        if (lane == 0) prefetch_l2((const char*)(gp + 128));
        if (lane == 1) prefetch_l2((const char*)(pp + 128));
    }

    for (int ch = cA; ch < cB; ch++) {
        const bool fullc = (ch < nfull);
        const bool vg = fullc || (rg < n);
        const bool v8 = fullc || (rg + 8 < n);
        const float4 z4 = make_float4(0.f, 0.f, 0.f, 0.f);

        // ---- A loads: 8x LDG.128 streaming, front-batched (rows rg, rg+8) ----
        float4 aL[4], aH[4];
        if (fullc) {
            #pragma unroll
            for (int S = 0; S < 4; S++) aL[S] = __ldcs(hgp + 4 * S);
            #pragma unroll
            for (int S = 0; S < 4; S++) aH[S] = __ldcs(hgp + 128 + 4 * S);
        } else {
            #pragma unroll
            for (int S = 0; S < 4; S++) aL[S] = vg ? __ldcs(hgp + 4 * S) : z4;
            #pragma unroll
            for (int S = 0; S < 4; S++) aH[S] = v8 ? __ldcs(hgp + 128 + 4 * S) : z4;
        }

        // ---- prefetch chunk ch+2 into L2 (no regs, no scoreboard) ----
        if (ch + 2 < nfull) {
            prefetch_l2(pfb + 65536);                 // 2 chunks * 32768 B ahead
            if (lane == 0) prefetch_l2((const char*)(gp + 256));
            if (lane == 1) prefetch_l2((const char*)(pp + 256));
        }

        float d2a = 0.f, d2b = 0.f;
        if (vg) {
            float2 gg = __ldcs(gp), qq = __ldcs(pp);
            float dx = gg.x - qq.x, dy = gg.y - qq.y;
            d2a = sqrtf(dx * dx + dy * dy);
        }
        if (v8) {
            float2 gg = __ldcs(gp + 8), qq = __ldcs(pp + 8);
            float dx = gg.x - qq.x, dy = gg.y - qq.y;
            d2b = sqrtf(dx * dx + dy * dy);
        }

        // ---- convert A to fp16 fragments ----
        uint32_t a0[4], a1[4], a2[4], a3[4];
        #pragma unroll
        for (int S = 0; S < 4; S++) {
            a0[S] = pack_h2(aL[S].x, aL[S].y);
            a2[S] = pack_h2(aL[S].z, aL[S].w);
            a1[S] = pack_h2(aH[S].x, aH[S].y);
            a3[S] = pack_h2(aH[S].z, aH[S].w);
        }

        // ---- 32 MMAs: 4 S x 8 n-tiles, all operands in registers ----
        float acc[8][4] = {{0,0,0,0},{0,0,0,0},{0,0,0,0},{0,0,0,0},
                           {0,0,0,0},{0,0,0,0},{0,0,0,0},{0,0,0,0}};
        #pragma unroll
        for (int S = 0; S < 4; S++) {
            #pragma unroll
            for (int nt = 0; nt < 8; nt++)
                mma_f16(acc[nt], a0[S], a1[S], a2[S], a3[S], bf[nt][S].x, bf[nt][S].y);
        }

        // ---- epilogue: four streaming STG.128 per row ----
        #pragma unroll
        for (int sgg = 0; sgg < 4; sgg++) {
            const int f4i = sgg * 4 + tau;
            float4 cc = sC4[f4i];
            float4 uu = sU4[f4i];
            if (vg) {
                float4 o;
                o.x = sigmoid_fast(fmaf(d2a, uu.x, acc[2*sgg][0]   + cc.x));
                o.y = sigmoid_fast(fmaf(d2a, uu.y, acc[2*sgg][1]   + cc.y));
                o.z = sigmoid_fast(fmaf(d2a, uu.z, acc[2*sgg+1][0] + cc.z));
                o.w = sigmoid_fast(fmaf(d2a, uu.w, acc[2*sgg+1][1] + cc.w));
                __stcs(op + f4i, o);
            }
            if (v8) {
                float4 o;
                o.x = sigmoid_fast(fmaf(d2b, uu.x, acc[2*sgg][2]   + cc.x));
                o.y = sigmoid_fast(fmaf(d2b, uu.y, acc[2*sgg][3]   + cc.y));
                o.z = sigmoid_fast(fmaf(d2b, uu.z, acc[2*sgg+1][2] + cc.z));
                o.w = sigmoid_fast(fmaf(d2b, uu.w, acc[2*sgg+1][3] + cc.w));
                __stcs(op + 128 + f4i, o);
            }
        }

        rg  += 128;
        hgp += 2048;    // 128 rows * 16 float4
        pfb += 32768;
        gp  += 128;
        pp  += 128;
        op  += 2048;
    }

    // ---- row-idx pass-through fixup (owning CTA only, after its stores) ----
    {
        const int cidx = idx >> 7;                  // chunk containing row idx
        if (cidx >= cA && cidx < cB) {              // CTA-uniform condition
            __syncthreads();                        // order vs this CTA's stores
            if (t < 16)
                out4[(size_t)idx * 16 + t] = h4[(size_t)idx * 16 + t];
        }
    }
}

// ---------------- launch ----------------

extern "C" void kernel_launch(void* const* d_in, const int* in_sizes, int n_in,
                              void* d_out, int out_size)
{
    const float* h    = (const float*)d_in[0];  // (N, 64)
    const float* ghs  = (const float*)d_in[1];  // (64,)
    const float* goal = (const float*)d_in[2];  // (N, 2)
    const float* pos  = (const float*)d_in[3];  // (N, 2)
    const float* Wemb = (const float*)d_in[4];  // (32, 2)
    const float* bemb = (const float*)d_in[5];  // (32,)
    const float* Wfc  = (const float*)d_in[6];  // (64, 192)
    const float* bfc  = (const float*)d_in[7];  // (64,)
    const int*   idx  = (const int*)d_in[8];    // scalar
    float* out = (float*)d_out;                 // N*64 h_out then 64 goal_out

    int n = in_sizes[0] / HDIM;
    int nch = (n + 127) / 128;
    int grid = 296;                              // 148 SMs x 2 CTAs (persistent)
    if (grid > nch) grid = nch;

    gate_kernel<<<grid, 256>>>(h, ghs, goal, pos, Wemb, bemb, Wfc, bfc, idx, out, n);
}